// round 10
// baseline (speedup 1.0000x reference)
#include <cuda_runtime.h>
#include <cstdint>

#define T_STEPS 2048
#define B_SZ    16
#define D_SZ    1024
#define BD      (B_SZ*D_SZ)          /* 16384 */
#define NCTA    128
#define NTHR    512
#define BG_N    4                    /* batch rows per CTA */
#define CG_N    32                   /* columns per CTA */
#define GROUPS  4                    /* independent sync domains */
#define ARR_STEP (32*4)              /* arrivals per step per group */

// 128 MB scratch for the precomputed input projection (allowed: __device__ global)
__device__ float    g_xp[(size_t)T_STEPS * BD];
// one monotonic arrival counter per batch-group, padded to separate L2 lines
__device__ unsigned g_cnt[GROUPS * 32];

// ---------------- packed fp32x2 helpers (sm_100+ PTX) ----------------
__device__ __forceinline__ void ffma2(unsigned long long &d,
                                      unsigned long long a,
                                      unsigned long long b) {
    asm("fma.rn.f32x2 %0, %1, %2, %0;" : "+l"(d) : "l"(a), "l"(b));
}
__device__ __forceinline__ unsigned long long dup2(float a) {
    unsigned long long r;
    asm("mov.b64 %0, {%1, %1};" : "=l"(r) : "f"(a));
    return r;
}
__device__ __forceinline__ float2 unpack2(unsigned long long v) {
    float2 r;
    asm("mov.b64 {%0, %1}, %2;" : "=f"(r.x), "=f"(r.y) : "l"(v));
    return r;
}

// ---------------- sync primitives ----------------
__device__ __forceinline__ unsigned ld_acq(const unsigned* p) {
    unsigned v;
    asm volatile("ld.acquire.gpu.global.u32 %0, [%1];" : "=r"(v) : "l"(p) : "memory");
    return v;
}
__device__ __forceinline__ void red_rel(unsigned* p) {
    asm volatile("red.add.release.gpu.global.u32 [%0], 1;" :: "l"(p) : "memory");
}
__device__ __forceinline__ unsigned ld_acq_sh(uint32_t a) {
    unsigned v;
    asm volatile("ld.acquire.cta.shared.u32 %0, [%1];" : "=r"(v) : "r"(a) : "memory");
    return v;
}
__device__ __forceinline__ void st_rel_sh(uint32_t a, unsigned v) {
    asm volatile("st.release.cta.shared.u32 [%0], %1;" :: "r"(a), "r"(v) : "memory");
}

__global__ void init_kernel() {
    if (threadIdx.x < GROUPS * 32) g_cnt[threadIdx.x] = 0u;
}

// ---------------------------------------------------------------------
// Kernel 1: xp[m,e] = sum_d x[m,d]*Wx[e,d] + b[e]   (unchanged)
// ---------------------------------------------------------------------
__global__ __launch_bounds__(256) void xp_gemm_kernel(
    const float* __restrict__ X,
    const float* __restrict__ Wx,
    const float* __restrict__ bias)
{
    __shared__ __align__(16) float As[16][68];
    __shared__ __align__(16) float Bs[16][68];

    const int tid   = threadIdx.x;
    const int mBase = blockIdx.y * 64;
    const int nBase = blockIdx.x * 64;

    const int lrow = tid >> 2;
    const int lk4  = (tid & 3) << 2;
    const int ty = tid >> 4;
    const int tx = tid & 15;

    unsigned long long acc[4][2];
#pragma unroll
    for (int i = 0; i < 4; i++) { acc[i][0] = 0ull; acc[i][1] = 0ull; }

    for (int k0 = 0; k0 < 1024; k0 += 16) {
        float4 av = *reinterpret_cast<const float4*>(
            &X[(size_t)(mBase + lrow) * 1024 + k0 + lk4]);
        float4 bv = *reinterpret_cast<const float4*>(
            &Wx[(size_t)(nBase + lrow) * 1024 + k0 + lk4]);
        As[lk4 + 0][lrow] = av.x; As[lk4 + 1][lrow] = av.y;
        As[lk4 + 2][lrow] = av.z; As[lk4 + 3][lrow] = av.w;
        Bs[lk4 + 0][lrow] = bv.x; Bs[lk4 + 1][lrow] = bv.y;
        Bs[lk4 + 2][lrow] = bv.z; Bs[lk4 + 3][lrow] = bv.w;
        __syncthreads();

#pragma unroll
        for (int k = 0; k < 16; k++) {
            float4 a = *reinterpret_cast<const float4*>(&As[k][ty << 2]);
            ulonglong2 bp = *reinterpret_cast<const ulonglong2*>(&Bs[k][tx << 2]);
            unsigned long long a0 = dup2(a.x), a1 = dup2(a.y);
            unsigned long long a2 = dup2(a.z), a3 = dup2(a.w);
            ffma2(acc[0][0], a0, bp.x); ffma2(acc[0][1], a0, bp.y);
            ffma2(acc[1][0], a1, bp.x); ffma2(acc[1][1], a1, bp.y);
            ffma2(acc[2][0], a2, bp.x); ffma2(acc[2][1], a2, bp.y);
            ffma2(acc[3][0], a3, bp.x); ffma2(acc[3][1], a3, bp.y);
        }
        __syncthreads();
    }

    const int col = nBase + (tx << 2);
    const float4 bv = *reinterpret_cast<const float4*>(&bias[col]);
#pragma unroll
    for (int m = 0; m < 4; m++) {
        const int row = mBase + (ty << 2) + m;
        float2 c01 = unpack2(acc[m][0]);
        float2 c23 = unpack2(acc[m][1]);
        float4 r;
        r.x = c01.x + bv.x; r.y = c01.y + bv.y;
        r.z = c23.x + bv.z; r.w = c23.y + bv.w;
        *reinterpret_cast<float4*>(&g_xp[(size_t)row * 1024 + col]) = r;
    }
}

// ---------------------------------------------------------------------
// Kernel 2: persistent recurrence, per-warp dataflow.
// 128 CTAs x 512 threads = 4 independent groups (bg = cta&3, 4 b-rows)
// x 32 col-slices (ng = cta>>2, 32 cols). No SMEM staging: each warp
// (k-slice of 64) reads h[t] directly from L2 via warp-uniform LDG.128
// (one sector request, lane-broadcast), interleaved with its FFMA2s.
// ONE __syncthreads per step (before cross-warp reduce; reduce buffer
// double-buffered by t&1). Producer arrivals are per-epilogue-warp
// (syncwarp + lane0 red.release) -> 128 arrivals/step/group; consumer
// detection by dedicated relay warp 15 polling the group counter and
// republishing through an smem flag (release.cta / acquire.cta chain).
// ---------------------------------------------------------------------
__global__ __launch_bounds__(512, 1) void recur_kernel(
    const float* __restrict__ Z,
    const float* __restrict__ H0,
    const float* __restrict__ Wh,
    const float* __restrict__ Gz,
    const float* __restrict__ Gh,
    const float* __restrict__ Bg,
    float* __restrict__ Out,
    float* __restrict__ Hout)
{
    extern __shared__ __align__(16) float sm[];
    float* red = sm;                        // [2][16][4][32] = 4096 floats
    unsigned* sflag = (unsigned*)(sm + 4096);

    const int tid  = threadIdx.x;
    const int ks   = tid >> 5;              // k-sixteenth 0..15 (= warp)
    const int lane = tid & 31;              // column within CTA
    const int cta  = blockIdx.x;

    const int bg    = cta & 3;              // batch group (independent domain)
    const int ng    = cta >> 2;             // column slice 0..31
    const int bbase = bg * BG_N;
    const int gcol  = ng * CG_N + lane;

    unsigned* cnt = &g_cnt[bg * 32];
    const uint32_t flag_sh = (uint32_t)__cvta_generic_to_shared(sflag);

    // ---- W_h slice (64 floats) -> registers, resident for all steps ----
    unsigned long long wx[16], wy[16];
    {
        const float* wp = Wh + (size_t)gcol * 1024 + ks * 64;
#pragma unroll
        for (int i = 0; i < 16; i++) {
            ulonglong2 v = *reinterpret_cast<const ulonglong2*>(wp + i * 4);
            wx[i] = v.x; wy[i] = v.y;
        }
    }

    // ---- epilogue role: warp w (0..3) owns b-row bbase+w, lane = col ----
    const bool is_epi = (ks < 4);
    const int  egb    = bbase + ks;         // valid when is_epi
    float gz_r = 0.f, gh_r = 0.f, bg_r = 0.f;
    if (is_epi) {
        gz_r = Gz[gcol]; gh_r = Gh[gcol]; bg_r = Bg[gcol];
    }

    if (tid == 0) *sflag = 0u;

    // ---- h[0] = h0 (required output row 0; also the t=0 source) ----
    if (is_epi)
        __stcg(&Hout[(size_t)egb * 1024 + gcol], H0[(size_t)egb * 1024 + gcol]);
    __syncthreads();                        // sflag + h0 stores ordered
    if (is_epi && lane == 0) red_rel(cnt);  // 4 arrivals/CTA -> 128/group

    for (int t = 0; t < T_STEPS; ++t) {
        const unsigned want = (unsigned)(t + 1);

        // ---- readiness: relay warp polls L2 counter, others poll smem ----
        if (ks == 15) {
            if (lane == 0) {
                while (ld_acq(cnt) < (unsigned)ARR_STEP * want) { }
                st_rel_sh(flag_sh, want);
            }
            __syncwarp();
        } else {
            if (lane == 0) {
                while (ld_acq_sh(flag_sh) < want) { }
            }
            __syncwarp();
        }

        // ---- epilogue operand prefetch (hidden under compute) ----
        float xpv = 0.f, zv = 0.f;
        size_t eidx = 0;
        if (is_epi) {
            eidx = (size_t)t * BD + (size_t)egb * 1024 + gcol;
            xpv = __ldcg(&g_xp[eidx]);
            zv  = __ldcg(&Z[eidx]);
        }

        // ---- compute: 64 warp-uniform LDG.128 + 128 ffma2 per lane ----
        const float* hk = Hout + (size_t)t * BD + (size_t)bbase * 1024 + ks * 64;
        unsigned long long accA[4] = {0ull, 0ull, 0ull, 0ull};
        unsigned long long accB[4] = {0ull, 0ull, 0ull, 0ull};
#pragma unroll
        for (int i = 0; i < 16; i++) {
#pragma unroll
            for (int b = 0; b < 4; b++) {
                ulonglong2 hv = __ldcg(reinterpret_cast<const ulonglong2*>(
                    hk + b * 1024 + i * 4));
                ffma2(accA[b], hv.x, wx[i]);
                ffma2(accB[b], hv.y, wy[i]);
            }
        }

        // ---- partials -> red[t&1][ks][b][n] (conflict-free, coalesced) ----
        float* rbuf = red + (t & 1) * 2048;
#pragma unroll
        for (int b = 0; b < 4; b++) {
            float2 a = unpack2(accA[b]);
            float2 c = unpack2(accB[b]);
            rbuf[ks * 128 + b * 32 + lane] = (a.x + a.y) + (c.x + c.y);
        }
        __syncthreads();    // the ONLY full-CTA barrier per step

        // ---- epilogue warps: reduce 16 k-partials, activation, store ----
        if (is_epi) {
            float dot = 0.f;
#pragma unroll
            for (int k = 0; k < 16; k++)
                dot += rbuf[k * 128 + ks * 32 + lane];
            const float hn  = tanhf(xpv + dot);
            __stcg(&Hout[(size_t)(t + 1) * BD + (size_t)egb * 1024 + gcol], hn);
            __syncwarp();
            if (lane == 0) red_rel(cnt);    // publish this b-row slice

            // gate + Out store: off the critical path (after arrive)
            const float pre = zv * gz_r + hn * gh_r + bg_r;
            const float sg  = 1.0f / (1.0f + __expf(-pre));
            __stcg(&Out[eidx], hn * (pre * sg));
        }
        // non-epilogue warps loop immediately (relay warp resumes polling)
    }
}

// ---------------------------------------------------------------------
extern "C" void kernel_launch(void* const* d_in, const int* in_sizes, int n_in,
                              void* d_out, int out_size)
{
    const float* x  = (const float*)d_in[0];
    const float* z  = (const float*)d_in[1];
    const float* h0 = (const float*)d_in[2];
    const float* Wx = (const float*)d_in[3];
    const float* Wh = (const float*)d_in[4];
    const float* b  = (const float*)d_in[5];
    const float* gz = (const float*)d_in[6];
    const float* gh = (const float*)d_in[7];
    const float* bg = (const float*)d_in[8];

    float* out  = (float*)d_out;                       // [T,B,D]
    float* hout = out + (size_t)T_STEPS * BD;          // [T+1,B,D]

    init_kernel<<<1, 128>>>();                         // zero group counters

    dim3 gGemm(1024 / 64, (T_STEPS * B_SZ) / 64);      // (16, 512)
    xp_gemm_kernel<<<gGemm, 256>>>(x, Wx, b);

    // actual need ~16.5KB; pad to force 1 CTA/SM (all 128 CTAs resident,
    // required for the group counters to make progress).
    const int smem_bytes = 118784;
    cudaFuncSetAttribute(recur_kernel,
                         cudaFuncAttributeMaxDynamicSharedMemorySize, smem_bytes);
    recur_kernel<<<NCTA, NTHR, smem_bytes>>>(z, h0, Wh, gz, gh, bg, out, hout);
}

// round 11
// speedup vs baseline: 1.4466x; 1.4466x over previous
#include <cuda_runtime.h>
#include <cstdint>

#define T_STEPS 2048
#define B_SZ    16
#define D_SZ    1024
#define BD      (B_SZ*D_SZ)          /* 16384 */
#define NCTA    128
#define NTHR    512
#define BG_N    4                    /* batch rows per CTA */
#define CG_N    32                   /* columns per CTA */
#define GROUPS  4                    /* independent sync domains */
#define GSIZE   32                   /* CTAs per domain */

// 128 MB scratch for the precomputed input projection (allowed: __device__ global)
__device__ float    g_xp[(size_t)T_STEPS * BD];
// per-CTA progress flags: g_flagv[bg*32+ng] == v  <=>  that CTA's slice of
// h[v-1] is visible. One 128B line per group; distinct word per producer
// (no atomic serialization; consumers poll one word per lane).
__device__ unsigned g_flagv[GROUPS * GSIZE];

// ---------------- packed fp32x2 helpers (sm_100+ PTX) ----------------
__device__ __forceinline__ void ffma2(unsigned long long &d,
                                      unsigned long long a,
                                      unsigned long long b) {
    asm("fma.rn.f32x2 %0, %1, %2, %0;" : "+l"(d) : "l"(a), "l"(b));
}
__device__ __forceinline__ unsigned long long dup2(float a) {
    unsigned long long r;
    asm("mov.b64 %0, {%1, %1};" : "=l"(r) : "f"(a));
    return r;
}
__device__ __forceinline__ float2 unpack2(unsigned long long v) {
    float2 r;
    asm("mov.b64 {%0, %1}, %2;" : "=f"(r.x), "=f"(r.y) : "l"(v));
    return r;
}
__device__ __forceinline__ void cp16(uint32_t dst_smem, const void* src) {
    asm volatile("cp.async.cg.shared.global [%0], [%1], 16;"
                 :: "r"(dst_smem), "l"(src) : "memory");
}
#define CP_COMMIT() asm volatile("cp.async.commit_group;" ::: "memory")
#define CP_WAIT0()  asm volatile("cp.async.wait_group 0;" ::: "memory")

// ---------------- sync primitives ----------------
__device__ __forceinline__ unsigned ld_acq(const unsigned* p) {
    unsigned v;
    asm volatile("ld.acquire.gpu.global.u32 %0, [%1];" : "=r"(v) : "l"(p) : "memory");
    return v;
}
__device__ __forceinline__ void st_rel(unsigned* p, unsigned v) {
    asm volatile("st.release.gpu.global.u32 [%0], %1;"
                 :: "l"(p), "r"(v) : "memory");
}

__global__ void init_kernel() {
    if (threadIdx.x < GROUPS * GSIZE) g_flagv[threadIdx.x] = 0u;
}
__global__ void dummy_kernel() { }   // 1 pad launch: harness(2) + init,xp,dummy
                                     // puts recur at global launch idx 5 (ncu -s 5)

// ---------------------------------------------------------------------
// Kernel 1: xp[m,e] = sum_d x[m,d]*Wx[e,d] + b[e]   (unchanged)
// ---------------------------------------------------------------------
__global__ __launch_bounds__(256) void xp_gemm_kernel(
    const float* __restrict__ X,
    const float* __restrict__ Wx,
    const float* __restrict__ bias)
{
    __shared__ __align__(16) float As[16][68];
    __shared__ __align__(16) float Bs[16][68];

    const int tid   = threadIdx.x;
    const int mBase = blockIdx.y * 64;
    const int nBase = blockIdx.x * 64;

    const int lrow = tid >> 2;
    const int lk4  = (tid & 3) << 2;
    const int ty = tid >> 4;
    const int tx = tid & 15;

    unsigned long long acc[4][2];
#pragma unroll
    for (int i = 0; i < 4; i++) { acc[i][0] = 0ull; acc[i][1] = 0ull; }

    for (int k0 = 0; k0 < 1024; k0 += 16) {
        float4 av = *reinterpret_cast<const float4*>(
            &X[(size_t)(mBase + lrow) * 1024 + k0 + lk4]);
        float4 bv = *reinterpret_cast<const float4*>(
            &Wx[(size_t)(nBase + lrow) * 1024 + k0 + lk4]);
        As[lk4 + 0][lrow] = av.x; As[lk4 + 1][lrow] = av.y;
        As[lk4 + 2][lrow] = av.z; As[lk4 + 3][lrow] = av.w;
        Bs[lk4 + 0][lrow] = bv.x; Bs[lk4 + 1][lrow] = bv.y;
        Bs[lk4 + 2][lrow] = bv.z; Bs[lk4 + 3][lrow] = bv.w;
        __syncthreads();

#pragma unroll
        for (int k = 0; k < 16; k++) {
            float4 a = *reinterpret_cast<const float4*>(&As[k][ty << 2]);
            ulonglong2 bp = *reinterpret_cast<const ulonglong2*>(&Bs[k][tx << 2]);
            unsigned long long a0 = dup2(a.x), a1 = dup2(a.y);
            unsigned long long a2 = dup2(a.z), a3 = dup2(a.w);
            ffma2(acc[0][0], a0, bp.x); ffma2(acc[0][1], a0, bp.y);
            ffma2(acc[1][0], a1, bp.x); ffma2(acc[1][1], a1, bp.y);
            ffma2(acc[2][0], a2, bp.x); ffma2(acc[2][1], a2, bp.y);
            ffma2(acc[3][0], a3, bp.x); ffma2(acc[3][1], a3, bp.y);
        }
        __syncthreads();
    }

    const int col = nBase + (tx << 2);
    const float4 bv = *reinterpret_cast<const float4*>(&bias[col]);
#pragma unroll
    for (int m = 0; m < 4; m++) {
        const int row = mBase + (ty << 2) + m;
        float2 c01 = unpack2(acc[m][0]);
        float2 c23 = unpack2(acc[m][1]);
        float4 r;
        r.x = c01.x + bv.x; r.y = c01.y + bv.y;
        r.z = c23.x + bv.z; r.w = c23.y + bv.w;
        *reinterpret_cast<float4*>(&g_xp[(size_t)row * 1024 + col]) = r;
    }
}

// ---------------------------------------------------------------------
// Kernel 2: persistent recurrence (R7 structure + flag-vector sync +
// coalesced epilogue). 128 CTAs x 512 threads = 4 independent groups
// (bg = cta&3, 4 b-rows) x 32 col-slices (ng = cta>>2, 32 cols). Per
// step: cp.async-stage 16KB of h[t] (this CTA's 4 b-rows), 256 MACs/
// thread with register-resident W_h, cross-warp k-reduce via SMEM,
// epilogue (warp = b-row, fully coalesced). Sync: producers st.release
// their own flag word; consumer warp 0 polls 32 flags (one per lane).
// ---------------------------------------------------------------------
__global__ __launch_bounds__(512, 1) void recur_kernel(
    const float* __restrict__ Z,
    const float* __restrict__ H0,
    const float* __restrict__ Wh,
    const float* __restrict__ Gz,
    const float* __restrict__ Gh,
    const float* __restrict__ Bg,
    float* __restrict__ Out,
    float* __restrict__ Hout)
{
    extern __shared__ __align__(16) float sm[];
    float* h_s = sm;                       // 4096 floats (16KB): [4][1024]
    float* red = sm + 4 * 1024;            // 2048 floats (8KB): [16][4][32]

    const int tid  = threadIdx.x;
    const int ks   = tid >> 5;             // k-sixteenth 0..15 (= warp)
    const int n    = tid & 31;             // column within CTA 0..31
    const int cta  = blockIdx.x;

    const int bg    = cta & 3;             // batch group (independent domain)
    const int ng    = cta >> 2;            // column slice 0..31
    const int bbase = bg * BG_N;
    const int gcol  = ng * CG_N + n;

    unsigned* gflags   = &g_flagv[bg * GSIZE];   // this group's 32 flags
    unsigned* my_flag  = &g_flagv[bg * GSIZE + ng];

    // ---- W_h slice (64 floats) -> registers, resident for all steps ----
    unsigned long long wx[16], wy[16];
    {
        const float* wp = Wh + (size_t)gcol * 1024 + ks * 64;
#pragma unroll
        for (int i = 0; i < 16; i++) {
            ulonglong2 v = *reinterpret_cast<const ulonglong2*>(wp + i * 4);
            wx[i] = v.x; wy[i] = v.y;
        }
    }

    // ---- epilogue role (threads 0..127): warp = b-row, lane = column ----
    const int eb  = tid >> 5;              // local b 0..3 (= warp id)
    const int en  = tid & 31;              // local col 0..31
    const int egb = bbase + eb;
    const int egc = ng * CG_N + en;
    float gz_r = 0.f, gh_r = 0.f, bg_r = 0.f;
    if (tid < 128) {
        gz_r = Gz[egc]; gh_r = Gh[egc]; bg_r = Bg[egc];
        // h[0] = h0 (required output row 0; also the t=0 staging source)
        __stcg(&Hout[(size_t)egb * 1024 + egc], H0[(size_t)egb * 1024 + egc]);
    }
    __syncthreads();
    if (tid == 0) st_rel(my_flag, 1u);     // publish h[0] slice

    const uint32_t h_sh = (uint32_t)__cvta_generic_to_shared(h_s);

    for (int t = 0; t < T_STEPS; ++t) {
        // ---- prefetch epilogue operands (independent of h) ----
        float xpv = 0.f, zv = 0.f;
        size_t eidx = 0;
        if (tid < 128) {
            eidx = (size_t)t * BD + (size_t)egb * 1024 + egc;
            xpv = __ldcg(&g_xp[eidx]);
            zv  = __ldcg(&Z[eidx]);
        }

        // ---- group readiness: warp 0, one flag per lane (no atomics) ----
        if (tid < 32) {
            const unsigned want = (unsigned)(t + 1);
            while (ld_acq(&gflags[tid]) < want) { }
        }
        __syncthreads();                           // B1

        // ---- stage h[t] rows bbase..bbase+3 (16KB, fully coalesced) ----
        const float* hsrc = Hout + (size_t)t * BD + (size_t)bbase * 1024;
        cp16(h_sh + (uint32_t)tid * 16u,         hsrc + tid * 4);
        cp16(h_sh + (uint32_t)(tid + 512) * 16u, hsrc + (tid + 512) * 4);
        CP_COMMIT();
        CP_WAIT0();
        __syncthreads();                           // B2

        // ---- dot products: 256 MACs/thread (64k x 4b), h broadcast ----
        unsigned long long accA[4] = {0ull, 0ull, 0ull, 0ull};
        unsigned long long accB[4] = {0ull, 0ull, 0ull, 0ull};
        const float* hc = h_s + ks * 64;
#pragma unroll
        for (int i = 0; i < 16; i++) {
#pragma unroll
            for (int b = 0; b < 4; b++) {
                ulonglong2 hv = *reinterpret_cast<const ulonglong2*>(
                    hc + b * 1024 + i * 4);
                ffma2(accA[b], hv.x, wx[i]);
                ffma2(accB[b], hv.y, wy[i]);
            }
        }

        // ---- partials -> red[ks][b][n] (conflict-free, coalesced) ----
#pragma unroll
        for (int b = 0; b < 4; b++) {
            float2 a = unpack2(accA[b]);
            float2 c = unpack2(accB[b]);
            red[ks * 128 + b * 32 + n] = (a.x + a.y) + (c.x + c.y);
        }
        __syncthreads();                           // B3

        // ---- final reduce (16 coalesced reads) + h store ----
        float hn = 0.f, pre = 0.f;
        if (tid < 128) {
            float dot = 0.f;
#pragma unroll
            for (int k = 0; k < 16; k++)
                dot += red[k * 128 + tid];          // [k][eb][en], coalesced
            hn  = tanhf(xpv + dot);
            __stcg(&Hout[(size_t)(t + 1) * BD + (size_t)egb * 1024 + egc], hn);
            pre = zv * gz_r + hn * gh_r + bg_r;
        }
        __syncthreads();                           // B4 (stores before publish)

        // ---- publish h[t+1] slice (plain release store, no atomic) ----
        if (tid == 0) st_rel(my_flag, (unsigned)(t + 2));

        // ---- gate + Out store: off the critical path ----
        if (tid < 128) {
            const float sg = 1.0f / (1.0f + __expf(-pre));
            __stcg(&Out[eidx], hn * (pre * sg));
        }
    }
}

// ---------------------------------------------------------------------
extern "C" void kernel_launch(void* const* d_in, const int* in_sizes, int n_in,
                              void* d_out, int out_size)
{
    const float* x  = (const float*)d_in[0];
    const float* z  = (const float*)d_in[1];
    const float* h0 = (const float*)d_in[2];
    const float* Wx = (const float*)d_in[3];
    const float* Wh = (const float*)d_in[4];
    const float* b  = (const float*)d_in[5];
    const float* gz = (const float*)d_in[6];
    const float* gh = (const float*)d_in[7];
    const float* bg = (const float*)d_in[8];

    float* out  = (float*)d_out;                       // [T,B,D]
    float* hout = out + (size_t)T_STEPS * BD;          // [T+1,B,D]

    init_kernel<<<1, 128>>>();                         // my launch 0

    dim3 gGemm(1024 / 64, (T_STEPS * B_SZ) / 64);      // (16, 512)
    xp_gemm_kernel<<<gGemm, 256>>>(x, Wx, b);          // my launch 1

    dummy_kernel<<<1, 1>>>();                          // my launch 2 (pad:
                                                       // harness has 2 pre-
                                                       // launches -> recur=idx5)

    // actual need 24KB; pad to force 1 CTA/SM (all 128 CTAs resident,
    // required for the group flags to make progress).
    const int smem_bytes = 118784;
    cudaFuncSetAttribute(recur_kernel,
                         cudaFuncAttributeMaxDynamicSharedMemorySize, smem_bytes);
    recur_kernel<<<NCTA, NTHR, smem_bytes>>>(z, h0, Wh, gz, gh, bg, out, hout);
}

// round 12
// speedup vs baseline: 1.4523x; 1.0039x over previous
#include <cuda_runtime.h>
#include <cstdint>

#define T_STEPS 2048
#define B_SZ    16
#define D_SZ    1024
#define BD      (B_SZ*D_SZ)          /* 16384 */
#define NCTA    128
#define NTHR    512
#define BG_N    4                    /* batch rows per CTA */
#define CG_N    32                   /* columns per CTA */
#define GROUPS  4                    /* independent sync domains */
#define GSIZE   32                   /* CTAs per domain */
#define FSTRIDE 32                   /* words between flags (128B lines) */

// 128 MB scratch for the precomputed input projection (allowed: __device__ global)
__device__ float    g_xp[(size_t)T_STEPS * BD];
// per-CTA progress flags, one 128B line each: g_flagv[(bg*32+p)*32] == v
// <=> producer p of group bg has published h[v-1]. Monotonic.
__device__ unsigned g_flagv[GROUPS * GSIZE * FSTRIDE];

// ---------------- packed fp32x2 helpers (sm_100+ PTX) ----------------
__device__ __forceinline__ void ffma2(unsigned long long &d,
                                      unsigned long long a,
                                      unsigned long long b) {
    asm("fma.rn.f32x2 %0, %1, %2, %0;" : "+l"(d) : "l"(a), "l"(b));
}
__device__ __forceinline__ unsigned long long dup2(float a) {
    unsigned long long r;
    asm("mov.b64 %0, {%1, %1};" : "=l"(r) : "f"(a));
    return r;
}
__device__ __forceinline__ float2 unpack2(unsigned long long v) {
    float2 r;
    asm("mov.b64 {%0, %1}, %2;" : "=f"(r.x), "=f"(r.y) : "l"(v));
    return r;
}
__device__ __forceinline__ void cp16(uint32_t dst_smem, const void* src) {
    asm volatile("cp.async.cg.shared.global [%0], [%1], 16;"
                 :: "r"(dst_smem), "l"(src) : "memory");
}
#define CP_COMMIT() asm volatile("cp.async.commit_group;" ::: "memory")
#define CP_WAIT0()  asm volatile("cp.async.wait_group 0;" ::: "memory")

// ---------------- sync primitives ----------------
__device__ __forceinline__ unsigned ld_acq(const unsigned* p) {
    unsigned v;
    asm volatile("ld.acquire.gpu.global.u32 %0, [%1];" : "=r"(v) : "l"(p) : "memory");
    return v;
}
__device__ __forceinline__ void st_rel(unsigned* p, unsigned v) {
    asm volatile("st.release.gpu.global.u32 [%0], %1;"
                 :: "l"(p), "r"(v) : "memory");
}
__device__ __forceinline__ void bar_sync_id(int id, int cnt) {
    asm volatile("bar.sync %0, %1;" :: "r"(id), "r"(cnt) : "memory");
}
__device__ __forceinline__ void bar_arrive_id(int id, int cnt) {
    asm volatile("bar.arrive %0, %1;" :: "r"(id), "r"(cnt) : "memory");
}

__global__ void init_kernel() {
    for (int i = threadIdx.x; i < GROUPS * GSIZE * FSTRIDE; i += blockDim.x)
        g_flagv[i] = 0u;
}
__global__ void dummy_kernel() { }   // pad: recur stays at ncu launch idx 5

// ---------------------------------------------------------------------
// Kernel 1: xp[m,e] = sum_d x[m,d]*Wx[e,d] + b[e]   (unchanged)
// ---------------------------------------------------------------------
__global__ __launch_bounds__(256) void xp_gemm_kernel(
    const float* __restrict__ X,
    const float* __restrict__ Wx,
    const float* __restrict__ bias)
{
    __shared__ __align__(16) float As[16][68];
    __shared__ __align__(16) float Bs[16][68];

    const int tid   = threadIdx.x;
    const int mBase = blockIdx.y * 64;
    const int nBase = blockIdx.x * 64;

    const int lrow = tid >> 2;
    const int lk4  = (tid & 3) << 2;
    const int ty = tid >> 4;
    const int tx = tid & 15;

    unsigned long long acc[4][2];
#pragma unroll
    for (int i = 0; i < 4; i++) { acc[i][0] = 0ull; acc[i][1] = 0ull; }

    for (int k0 = 0; k0 < 1024; k0 += 16) {
        float4 av = *reinterpret_cast<const float4*>(
            &X[(size_t)(mBase + lrow) * 1024 + k0 + lk4]);
        float4 bv = *reinterpret_cast<const float4*>(
            &Wx[(size_t)(nBase + lrow) * 1024 + k0 + lk4]);
        As[lk4 + 0][lrow] = av.x; As[lk4 + 1][lrow] = av.y;
        As[lk4 + 2][lrow] = av.z; As[lk4 + 3][lrow] = av.w;
        Bs[lk4 + 0][lrow] = bv.x; Bs[lk4 + 1][lrow] = bv.y;
        Bs[lk4 + 2][lrow] = bv.z; Bs[lk4 + 3][lrow] = bv.w;
        __syncthreads();

#pragma unroll
        for (int k = 0; k < 16; k++) {
            float4 a = *reinterpret_cast<const float4*>(&As[k][ty << 2]);
            ulonglong2 bp = *reinterpret_cast<const ulonglong2*>(&Bs[k][tx << 2]);
            unsigned long long a0 = dup2(a.x), a1 = dup2(a.y);
            unsigned long long a2 = dup2(a.z), a3 = dup2(a.w);
            ffma2(acc[0][0], a0, bp.x); ffma2(acc[0][1], a0, bp.y);
            ffma2(acc[1][0], a1, bp.x); ffma2(acc[1][1], a1, bp.y);
            ffma2(acc[2][0], a2, bp.x); ffma2(acc[2][1], a2, bp.y);
            ffma2(acc[3][0], a3, bp.x); ffma2(acc[3][1], a3, bp.y);
        }
        __syncthreads();
    }

    const int col = nBase + (tx << 2);
    const float4 bv = *reinterpret_cast<const float4*>(&bias[col]);
#pragma unroll
    for (int m = 0; m < 4; m++) {
        const int row = mBase + (ty << 2) + m;
        float2 c01 = unpack2(acc[m][0]);
        float2 c23 = unpack2(acc[m][1]);
        float4 r;
        r.x = c01.x + bv.x; r.y = c01.y + bv.y;
        r.z = c23.x + bv.z; r.w = c23.y + bv.w;
        *reinterpret_cast<float4*>(&g_xp[(size_t)row * 1024 + col]) = r;
    }
}

// ---------------------------------------------------------------------
// Kernel 2: persistent recurrence, WARP-grained dataflow.
// 128 CTAs x 512 threads = 4 groups (bg = cta&3, 4 b-rows) x 32 col-
// slices (ng = cta>>2, 32 cols). Warp ks consumes only producers
// {2ks, 2ks+1}: polls just those 2 flags, cp.asyncs its own 1KB h
// slice, computes, deposits partials. Cross-warp convergence is ONE
// producer/consumer named barrier (warps 4-15 bar.arrive and run
// ahead; epi warps 0-3 bar.sync). Barrier id alternates with t&1;
// reduce buffer double-buffered (phase-aliasing & WAR proven safe via
// the all-producers transitive dependency of every epilogue).
// ---------------------------------------------------------------------
__global__ __launch_bounds__(512, 1) void recur_kernel(
    const float* __restrict__ Z,
    const float* __restrict__ H0,
    const float* __restrict__ Wh,
    const float* __restrict__ Gz,
    const float* __restrict__ Gh,
    const float* __restrict__ Bg,
    float* __restrict__ Out,
    float* __restrict__ Hout)
{
    extern __shared__ __align__(16) float sm[];
    float* h_s = sm;                       // [16 warps][4 rows][64] = 4096 f
    float* red = sm + 4096;                // [2][16][4][32] = 4096 f

    const int tid  = threadIdx.x;
    const int ks   = tid >> 5;             // k-sixteenth 0..15 (= warp)
    const int lane = tid & 31;             // column within CTA
    const int cta  = blockIdx.x;

    const int bg    = cta & 3;             // batch group (independent domain)
    const int ng    = cta >> 2;            // column slice 0..31
    const int bbase = bg * BG_N;
    const int gcol  = ng * CG_N + lane;

    unsigned* my_flag = &g_flagv[(bg * GSIZE + ng) * FSTRIDE];
    // the 2 producers this warp depends on (lane 0 / lane 1 poll one each)
    const unsigned* dep_flag =
        &g_flagv[(bg * GSIZE + (2 * ks + (lane & 1))) * FSTRIDE];

    // ---- W_h slice (64 floats) -> registers, resident for all steps ----
    unsigned long long wx[16], wy[16];
    {
        const float* wp = Wh + (size_t)gcol * 1024 + ks * 64;
#pragma unroll
        for (int i = 0; i < 16; i++) {
            ulonglong2 v = *reinterpret_cast<const ulonglong2*>(wp + i * 4);
            wx[i] = v.x; wy[i] = v.y;
        }
    }

    // ---- staging pieces (2 x 16B per lane into this warp's h_s slice) ----
    const uint32_t h_sh = (uint32_t)__cvta_generic_to_shared(h_s);
    const int r0 = lane >> 4,        c0 = lane & 15;
    const int r1 = (lane + 32) >> 4, c1 = (lane + 32) & 15;
    const uint32_t dst0 = h_sh + (uint32_t)(ks * 256 + r0 * 64 + c0 * 4) * 4u;
    const uint32_t dst1 = h_sh + (uint32_t)(ks * 256 + r1 * 64 + c1 * 4) * 4u;
    const int soff0 = (bbase + r0) * 1024 + ks * 64 + c0 * 4;
    const int soff1 = (bbase + r1) * 1024 + ks * 64 + c1 * 4;

    // ---- epilogue role: warps 0-3, warp = b-row, lane = column ----
    const bool is_epi = (ks < 4);
    const int  egb    = bbase + ks;        // valid when is_epi
    float gz_r = 0.f, gh_r = 0.f, bg_r = 0.f;
    if (is_epi) {
        gz_r = Gz[gcol]; gh_r = Gh[gcol]; bg_r = Bg[gcol];
        // h[0] = h0 (required output row 0; also the t=0 staging source)
        __stcg(&Hout[(size_t)egb * 1024 + gcol], H0[(size_t)egb * 1024 + gcol]);
    }
    __syncthreads();
    if (tid == 0) st_rel(my_flag, 1u);     // publish h[0] slice

    for (int t = 0; t < T_STEPS; ++t) {
        // ---- epilogue operand prefetch (completes under compute) ----
        float xpv = 0.f, zv = 0.f;
        size_t eidx = 0;
        if (is_epi) {
            eidx = (size_t)t * BD + (size_t)egb * 1024 + gcol;
            xpv = __ldcg(&g_xp[eidx]);
            zv  = __ldcg(&Z[eidx]);
        }

        // ---- per-warp readiness: poll only MY 2 producers ----
        const unsigned want = (unsigned)(t + 1);
        if (lane < 2) {
            while (ld_acq(dep_flag) < want) { }
        }
        __syncwarp();

        // ---- stage this warp's 1KB h slice (warp-local smem only) ----
        const float* hbase = Hout + (size_t)t * BD;
        cp16(dst0, hbase + soff0);
        cp16(dst1, hbase + soff1);
        CP_COMMIT();
        CP_WAIT0();
        __syncwarp();

        // ---- dot products: 256 MACs/lane, uniform LDS broadcast ----
        unsigned long long accA[4] = {0ull, 0ull, 0ull, 0ull};
        unsigned long long accB[4] = {0ull, 0ull, 0ull, 0ull};
        const float* hc = h_s + ks * 256;
#pragma unroll
        for (int i = 0; i < 16; i++) {
#pragma unroll
            for (int b = 0; b < 4; b++) {
                ulonglong2 hv = *reinterpret_cast<const ulonglong2*>(
                    hc + b * 64 + i * 4);
                ffma2(accA[b], hv.x, wx[i]);
                ffma2(accB[b], hv.y, wy[i]);
            }
        }

        // ---- partials -> red[t&1][ks][b][n] ----
        float* rbuf = red + (t & 1) * 2048;
#pragma unroll
        for (int b = 0; b < 4; b++) {
            float2 a = unpack2(accA[b]);
            float2 c = unpack2(accB[b]);
            rbuf[ks * 128 + b * 32 + lane] = (a.x + a.y) + (c.x + c.y);
        }

        const int barid = t & 1;
        if (!is_epi) {
            bar_arrive_id(barid, NTHR);    // non-blocking: run ahead to t+1
        } else {
            bar_sync_id(barid, NTHR);      // wait all 16 warps' partials

            // reduce 16 k-partials (coalesced), activation, h store
            float dot = 0.f;
#pragma unroll
            for (int k = 0; k < 16; k++)
                dot += rbuf[k * 128 + ks * 32 + lane];
            const float hn = tanhf(xpv + dot);
            __stcg(&Hout[(size_t)(t + 1) * BD + (size_t)egb * 1024 + gcol], hn);

            bar_sync_id(2, 128);           // all 4 b-rows stored
            if (tid == 0) st_rel(my_flag, (unsigned)(t + 2));

            // gate + Out store: off the critical path
            const float pre = zv * gz_r + hn * gh_r + bg_r;
            const float sg  = 1.0f / (1.0f + __expf(-pre));
            __stcg(&Out[eidx], hn * (pre * sg));
        }
    }
}

// ---------------------------------------------------------------------
extern "C" void kernel_launch(void* const* d_in, const int* in_sizes, int n_in,
                              void* d_out, int out_size)
{
    const float* x  = (const float*)d_in[0];
    const float* z  = (const float*)d_in[1];
    const float* h0 = (const float*)d_in[2];
    const float* Wx = (const float*)d_in[3];
    const float* Wh = (const float*)d_in[4];
    const float* b  = (const float*)d_in[5];
    const float* gz = (const float*)d_in[6];
    const float* gh = (const float*)d_in[7];
    const float* bg = (const float*)d_in[8];

    float* out  = (float*)d_out;                       // [T,B,D]
    float* hout = out + (size_t)T_STEPS * BD;          // [T+1,B,D]

    init_kernel<<<1, 1024>>>();                        // zero flags

    dim3 gGemm(1024 / 64, (T_STEPS * B_SZ) / 64);      // (16, 512)
    xp_gemm_kernel<<<gGemm, 256>>>(x, Wx, b);

    dummy_kernel<<<1, 1>>>();                          // keep recur at ncu idx 5

    // actual need 32KB; pad to force 1 CTA/SM (all 128 CTAs resident,
    // required for the dataflow flags to make progress).
    const int smem_bytes = 118784;
    cudaFuncSetAttribute(recur_kernel,
                         cudaFuncAttributeMaxDynamicSharedMemorySize, smem_bytes);
    recur_kernel<<<NCTA, NTHR, smem_bytes>>>(z, h0, Wh, gz, gh, bg, out, hout);
}